// round 6
// baseline (speedup 1.0000x reference)
#include <cuda_runtime.h>
#include <math.h>

#define N_SAMPLES 131072
#define N_EVENTS  128
#define N_ATOMS   32
#define ATOM_SIZE 512
#define LATENT    16
#define TIME_DIM  17
#define LAYERS    7

// ---------------- device-global scratch (no allocation allowed) ----------------
__device__ float g_xf[N_EVENTS * LATENT];            // final latent per event
__device__ int   g_pos[N_EVENTS];                    // dirac shift per event

// 16-term dot product, serial FMA chain in ascending index order.
// EXACTLY the same association order as the R3/R4 passing kernels so the
// argmax bit decisions are bit-identical.
__device__ __forceinline__ float dot16(float4 w0, float4 w1, float4 w2, float4 w3,
                                       float4 x0, float4 x1, float4 x2, float4 x3,
                                       float init)
{
    float v = init;
    v = fmaf(x0.x, w0.x, v); v = fmaf(x0.y, w0.y, v);
    v = fmaf(x0.z, w0.z, v); v = fmaf(x0.w, w0.w, v);
    v = fmaf(x1.x, w1.x, v); v = fmaf(x1.y, w1.y, v);
    v = fmaf(x1.z, w1.z, v); v = fmaf(x1.w, w1.w, v);
    v = fmaf(x2.x, w2.x, v); v = fmaf(x2.y, w2.y, v);
    v = fmaf(x2.z, w2.z, v); v = fmaf(x2.w, w2.w, v);
    v = fmaf(x3.x, w3.x, v); v = fmaf(x3.y, w3.y, v);
    v = fmaf(x3.z, w3.z, v); v = fmaf(x3.w, w3.w, v);
    return v;
}

// smem layout constants (floats)
#define WT_ELEMS (LAYERS * 68 * LATENT)   // 7616
#define WS_ELEMS (LAYERS * 32 * LATENT)   // 3584
#define BS_ELEMS (LAYERS * 32)            // 224
#define X_ELEMS  (N_EVENTS * LATENT)      // 2048
#define T_ELEMS  (N_EVENTS * 34)          // 4352
#define TREE_SMEM_FLOATS (WT_ELEMS + WS_ELEMS + BS_ELEMS + 2 * X_ELEMS + 2 * T_ELEMS)

// ---------------- K1: binary tree, (event,row)-parallel, smem-resident ---------
// 1024 threads. Per layer i, work items idx in [0, n*100):
//   e = idx/100; j = idx%100
//   j in [0,68)   : time-offset row  (child c=j/34, r=j%34)
//   j in [68,100) : latent split row
__global__ __launch_bounds__(1024, 1)
void tree_kernel(const float* __restrict__ base_latent,
                 const float* __restrict__ Wt,   // (7, 68, 16)
                 const float* __restrict__ Ws,   // (7, 32, 16)
                 const float* __restrict__ bs)   // (7, 32)
{
    extern __shared__ float sm[];
    float* wts = sm;                       // 7616
    float* wss = wts + WT_ELEMS;           // 3584
    float* bss = wss + WS_ELEMS;           // 224
    float* sx  = bss + BS_ELEMS;           // 2 * 2048
    float* st  = sx + 2 * X_ELEMS;         // 2 * 4352

    const int tid = threadIdx.x;           // 1024 threads

    // preload all weights (vectorized where aligned)
    {
        const float4* a = (const float4*)Wt;  float4* d = (float4*)wts;
        for (int k = tid; k < WT_ELEMS / 4; k += 1024) d[k] = a[k];
        const float4* a2 = (const float4*)Ws; float4* d2 = (float4*)wss;
        for (int k = tid; k < WS_ELEMS / 4; k += 1024) d2[k] = a2[k];
        if (tid < BS_ELEMS) bss[tid] = bs[tid];
    }
    if (tid < LATENT)       sx[tid] = base_latent[tid];
    if (tid < TIME_DIM * 2) st[tid] = 0.0f;
    __syncthreads();

    for (int i = 0; i < LAYERS; i++) {
        const int n = 1 << i;
        const float* xA = sx + (i & 1) * X_ELEMS;
        float*       xB = sx + ((i & 1) ^ 1) * X_ELEMS;
        const float* tA = st + (i & 1) * T_ELEMS;
        float*       tB = st + ((i & 1) ^ 1) * T_ELEMS;

        const int tot = n * 100;
        for (int idx = tid; idx < tot; idx += 1024) {
            const int e = idx / 100;
            const int j = idx - e * 100;
            const float4* xp = (const float4*)(xA + e * LATENT);
            const float4 x0 = xp[0], x1 = xp[1], x2 = xp[2], x3 = xp[3];
            if (j < 68) {
                const float4* wp = (const float4*)(wts + (i * 68 + j) * LATENT);
                const float v = dot16(wp[0], wp[1], wp[2], wp[3],
                                      x0, x1, x2, x3, 0.0f);
                const int c = j / 34, r = j - c * 34;
                tB[(2 * e + c) * 34 + r] = tA[e * 34 + r] + v;
            } else {
                const int jl = j - 68;
                const float4* wp = (const float4*)(wss + (i * 32 + jl) * LATENT);
                const float v = dot16(wp[0], wp[1], wp[2], wp[3],
                                      x0, x1, x2, x3, bss[i * 32 + jl]);
                xB[(2 * e + (jl >> 4)) * LATENT + (jl & 15)] = v;
            }
        }
        __syncthreads();
    }

    // LAYERS = 7 (odd) -> final buffers in parity 1
    const float* xF = sx + X_ELEMS;
    const float* tF = st + T_ELEMS;

    // export final latents
    for (int k = tid; k < X_ELEMS; k += 1024) g_xf[k] = xF[k];

    // argmax per event: strict >, MSB first (bit-identical to prior kernels)
    if (tid < N_EVENTS) {
        const int e = tid;
        int p = 0;
        #pragma unroll
        for (int t = 0; t < TIME_DIM; t++) {
            const int bit = tF[e * 34 + t * 2 + 1] > tF[e * 34 + t * 2 + 0];
            p |= bit << (TIME_DIM - 1 - t);
        }
        g_pos[e] = p;
    }
}

// ---------------- K2: fused waveform + deterministic scatter-gather ------------
// 256 blocks x 512 threads; block b owns output tile [b*512, b*512+512).
// For each event overlapping the tile (block-uniform decision), compute the
// full 512-sample scaled waveform and accumulate the shifted window.
__global__ __launch_bounds__(512, 2)
void wave_gather_kernel(const float* __restrict__ atoms,   // (32, 512)
                        const float* __restrict__ Wa,      // (32, 16)
                        const float* __restrict__ ba,      // (32,)
                        const float* __restrict__ Wamp,    // (1, 16)
                        const float* __restrict__ bamp,    // (1,)
                        float* __restrict__ out)
{
    __shared__ int   ps[N_EVENTS];
    __shared__ float cs[N_ATOMS];
    __shared__ float s_amp;
    __shared__ float s_red[16];
    __shared__ float wv[ATOM_SIZE];

    const int tid = threadIdx.x;                 // 512 threads
    const int t0  = blockIdx.x * ATOM_SIZE;
    const int t   = t0 + tid;

    if (tid < N_EVENTS) ps[tid] = g_pos[tid];
    __syncthreads();

    float acc = 0.0f;

    for (int e = 0; e < N_EVENTS; e++) {
        const int p = ps[e];
        // event e covers [p, p+512); tile covers [t0, t0+512) — block-uniform test
        if (p + ATOM_SIZE <= t0 || p >= t0 + ATOM_SIZE) continue;

        const float* xe = g_xf + e * LATENT;

        // coefficients + amplitude (same ascending-k order as before)
        if (tid < N_ATOMS) {
            float v = ba[tid];
            #pragma unroll
            for (int d = 0; d < LATENT; d++) v += xe[d] * Wa[tid * LATENT + d];
            cs[tid] = v;
        }
        if (tid == N_ATOMS) {
            float v = bamp[0];
            #pragma unroll
            for (int d = 0; d < LATENT; d++) v += xe[d] * Wamp[d];
            s_amp = v;
        }
        __syncthreads();

        // full waveform sample j = tid
        float v = 0.0f;
        #pragma unroll
        for (int k = 0; k < N_ATOMS; k++) v += cs[k] * atoms[k * ATOM_SIZE + tid];
        // Hamming window: 0.54 - 0.46*cos(2*pi*j/512)
        const float win = 0.54f - 0.46f * cospif((float)tid * (1.0f / 256.0f));
        v *= win;

        // block reduce sum of squares (16 warps)
        float sq = v * v;
        #pragma unroll
        for (int o = 16; o > 0; o >>= 1) sq += __shfl_xor_sync(0xffffffffu, sq, o);
        if ((tid & 31) == 0) s_red[tid >> 5] = sq;
        __syncthreads();
        float tot;
        {
            float r = (tid < 16) ? s_red[tid] : 0.0f;
            // broadcast-safe: every thread sums the 16 partials identically
            tot = s_red[0];
            #pragma unroll
            for (int w = 1; w < 16; w++) tot += s_red[w];
            (void)r;
        }
        const float scale = s_amp / (sqrtf(tot) + 1e-8f);

        wv[tid] = v * scale;
        __syncthreads();

        // accumulate shifted window: out sample t needs event sample (t - p)
        const unsigned off = (unsigned)(t - p);
        if (off < (unsigned)ATOM_SIZE) acc += wv[off];
        __syncthreads();   // before cs/wv reuse by next event
    }

    out[t] = acc;
}

// ---------------- launch -------------------------------------------------------
extern "C" void kernel_launch(void* const* d_in, const int* in_sizes, int n_in,
                              void* d_out, int out_size)
{
    // Robust input mapping by element count (all sizes unique except the two 16s,
    // where dict order gives base_latent before to_amp_W).
    const float *base_latent = nullptr, *Wt = nullptr, *Ws = nullptr, *bs = nullptr;
    const float *atoms = nullptr, *Wa = nullptr, *ba = nullptr, *Wamp = nullptr, *bamp = nullptr;
    for (int i = 0; i < n_in; i++) {
        const int s = in_sizes[i];
        const float* p = (const float*)d_in[i];
        switch (s) {
            case WT_ELEMS:              Wt = p;    break;   // 7616
            case WS_ELEMS:              Ws = p;    break;   // 3584
            case BS_ELEMS:              bs = p;    break;   // 224
            case N_ATOMS * ATOM_SIZE:   atoms = p; break;   // 16384
            case N_ATOMS * LATENT:      Wa = p;    break;   // 512
            case N_ATOMS:               ba = p;    break;   // 32
            case 1:                     bamp = p;  break;   // 1
            case LATENT:                                    // 16, twice
                if (!base_latent) base_latent = p; else Wamp = p;
                break;
            default: break;
        }
    }

    float* out = (float*)d_out;

    const int tree_smem = TREE_SMEM_FLOATS * (int)sizeof(float);   // ~94.6 KB
    cudaFuncSetAttribute(tree_kernel, cudaFuncAttributeMaxDynamicSharedMemorySize, tree_smem);

    tree_kernel<<<1, 1024, tree_smem>>>(base_latent, Wt, Ws, bs);
    wave_gather_kernel<<<N_SAMPLES / ATOM_SIZE, ATOM_SIZE>>>(atoms, Wa, ba, Wamp, bamp, out);
    (void)out_size;
}

// round 9
// speedup vs baseline: 4.0130x; 4.0130x over previous
#include <cuda_runtime.h>
#include <math.h>

#define N_SAMPLES 131072
#define N_EVENTS  128
#define N_ATOMS   32
#define ATOM_SIZE 512
#define LATENT    16
#define TIME_DIM  17
#define LAYERS    7

// ---------------- device-global scratch (no allocation allowed) ----------------
__device__ float g_xf[N_EVENTS * LATENT];            // final latent per event
__device__ int   g_pos[N_EVENTS];                    // dirac shift per event
__device__ float g_wave[N_EVENTS * ATOM_SIZE];       // pre-scaled waveforms

// 16-term dot product, serial FMA chain in ascending index order.
// EXACTLY the same association order as all prior passing kernels so the
// argmax bit decisions are bit-identical.
__device__ __forceinline__ float dot16(float4 w0, float4 w1, float4 w2, float4 w3,
                                       float4 x0, float4 x1, float4 x2, float4 x3,
                                       float init)
{
    float v = init;
    v = fmaf(x0.x, w0.x, v); v = fmaf(x0.y, w0.y, v);
    v = fmaf(x0.z, w0.z, v); v = fmaf(x0.w, w0.w, v);
    v = fmaf(x1.x, w1.x, v); v = fmaf(x1.y, w1.y, v);
    v = fmaf(x1.z, w1.z, v); v = fmaf(x1.w, w1.w, v);
    v = fmaf(x2.x, w2.x, v); v = fmaf(x2.y, w2.y, v);
    v = fmaf(x2.z, w2.z, v); v = fmaf(x2.w, w2.w, v);
    v = fmaf(x3.x, w3.x, v); v = fmaf(x3.y, w3.y, v);
    v = fmaf(x3.z, w3.z, v); v = fmaf(x3.w, w3.w, v);
    return v;
}

// smem layout constants (floats)
#define WT_ELEMS (LAYERS * 68 * LATENT)   // 7616
#define WS_ELEMS (LAYERS * 32 * LATENT)   // 3584
#define BS_ELEMS (LAYERS * 32)            // 224
#define X_ELEMS  (N_EVENTS * LATENT)      // 2048
#define T_ELEMS  (N_EVENTS * 34)          // 4352
#define TREE_SMEM_FLOATS (WT_ELEMS + WS_ELEMS + BS_ELEMS + 2 * X_ELEMS + 2 * T_ELEMS)

// ---------------- K1: binary tree, (event,row)-parallel, smem-resident ---------
// 1024 threads. Per layer i, work items idx in [0, n*100):
//   e = idx/100; j = idx%100
//   j in [0,68)   : time-offset row  (child c=j/34, r=j%34)
//   j in [68,100) : latent split row
__global__ __launch_bounds__(1024, 1)
void tree_kernel(const float* __restrict__ base_latent,
                 const float* __restrict__ Wt,   // (7, 68, 16)
                 const float* __restrict__ Ws,   // (7, 32, 16)
                 const float* __restrict__ bs)   // (7, 32)
{
    extern __shared__ float sm[];
    float* wts = sm;                       // 7616
    float* wss = wts + WT_ELEMS;           // 3584
    float* bss = wss + WS_ELEMS;           // 224
    float* sx  = bss + BS_ELEMS;           // 2 * 2048
    float* st  = sx + 2 * X_ELEMS;         // 2 * 4352

    const int tid = threadIdx.x;           // 1024 threads

    // preload all weights (vectorized)
    {
        const float4* a = (const float4*)Wt;  float4* d = (float4*)wts;
        for (int k = tid; k < WT_ELEMS / 4; k += 1024) d[k] = a[k];
        const float4* a2 = (const float4*)Ws; float4* d2 = (float4*)wss;
        for (int k = tid; k < WS_ELEMS / 4; k += 1024) d2[k] = a2[k];
        if (tid < BS_ELEMS) bss[tid] = bs[tid];
    }
    if (tid < LATENT)       sx[tid] = base_latent[tid];
    if (tid < TIME_DIM * 2) st[tid] = 0.0f;
    __syncthreads();

    for (int i = 0; i < LAYERS; i++) {
        const int n = 1 << i;
        const float* xA = sx + (i & 1) * X_ELEMS;
        float*       xB = sx + ((i & 1) ^ 1) * X_ELEMS;
        const float* tA = st + (i & 1) * T_ELEMS;
        float*       tB = st + ((i & 1) ^ 1) * T_ELEMS;

        const int tot = n * 100;
        for (int idx = tid; idx < tot; idx += 1024) {
            const int e = idx / 100;
            const int j = idx - e * 100;
            const float4* xp = (const float4*)(xA + e * LATENT);
            const float4 x0 = xp[0], x1 = xp[1], x2 = xp[2], x3 = xp[3];
            if (j < 68) {
                const float4* wp = (const float4*)(wts + (i * 68 + j) * LATENT);
                const float v = dot16(wp[0], wp[1], wp[2], wp[3],
                                      x0, x1, x2, x3, 0.0f);
                const int c = j / 34, r = j - c * 34;
                tB[(2 * e + c) * 34 + r] = tA[e * 34 + r] + v;
            } else {
                const int jl = j - 68;
                const float4* wp = (const float4*)(wss + (i * 32 + jl) * LATENT);
                const float v = dot16(wp[0], wp[1], wp[2], wp[3],
                                      x0, x1, x2, x3, bss[i * 32 + jl]);
                xB[(2 * e + (jl >> 4)) * LATENT + (jl & 15)] = v;
            }
        }
        __syncthreads();
    }

    // LAYERS = 7 (odd) -> final buffers in parity 1
    const float* xF = sx + X_ELEMS;
    const float* tF = st + T_ELEMS;

    // export final latents
    for (int k = tid; k < X_ELEMS; k += 1024) g_xf[k] = xF[k];

    // argmax per event: strict >, MSB first (bit-identical to prior kernels)
    if (tid < N_EVENTS) {
        const int e = tid;
        int p = 0;
        #pragma unroll
        for (int t = 0; t < TIME_DIM; t++) {
            const int bit = tF[e * 34 + t * 2 + 1] > tF[e * 34 + t * 2 + 0];
            p |= bit << (TIME_DIM - 1 - t);
        }
        g_pos[e] = p;
    }
}

// ---------------- K2: per-event waveform (coeffs, window, norm, amp) -----------
// One block per event — parallel across events, immune to position clustering.
__global__ void wave_kernel(const float* __restrict__ atoms,   // (32, 512)
                            const float* __restrict__ Wa,      // (32, 16)
                            const float* __restrict__ ba,      // (32,)
                            const float* __restrict__ Wamp,    // (1, 16)
                            const float* __restrict__ bamp)    // (1,)
{
    __shared__ float cs[N_ATOMS];
    __shared__ float s_amp;
    __shared__ float s_red[4];

    const int e   = blockIdx.x;
    const int tid = threadIdx.x;          // 128 threads
    const float* xe = g_xf + e * LATENT;

    if (tid < N_ATOMS) {
        float v = ba[tid];
        #pragma unroll
        for (int d = 0; d < LATENT; d++) v += xe[d] * Wa[tid * LATENT + d];
        cs[tid] = v;
    }
    if (tid == N_ATOMS) {
        float v = bamp[0];
        #pragma unroll
        for (int d = 0; d < LATENT; d++) v += xe[d] * Wamp[d];
        s_amp = v;
    }
    __syncthreads();

    float w[4];
    float sq = 0.0f;
    #pragma unroll
    for (int q = 0; q < 4; q++) {
        const int j = tid + q * 128;
        float v = 0.0f;
        #pragma unroll
        for (int k = 0; k < N_ATOMS; k++) v += cs[k] * atoms[k * ATOM_SIZE + j];
        // Hamming window: 0.54 - 0.46*cos(2*pi*j/512)
        const float win = 0.54f - 0.46f * cospif((float)j * (1.0f / 256.0f));
        v *= win;
        w[q] = v;
        sq += v * v;
    }

    // block reduce sum of squares (4 warps)
    #pragma unroll
    for (int o = 16; o > 0; o >>= 1) sq += __shfl_xor_sync(0xffffffffu, sq, o);
    if ((tid & 31) == 0) s_red[tid >> 5] = sq;
    __syncthreads();
    const float tot   = s_red[0] + s_red[1] + s_red[2] + s_red[3];
    const float scale = s_amp / (sqrtf(tot) + 1e-8f);

    #pragma unroll
    for (int q = 0; q < 4; q++)
        g_wave[e * ATOM_SIZE + tid + q * 128] = w[q] * scale;
}

// ---------------- K3: deterministic gather of shifted waveforms ---------------
// Bounded cost per tile: fixed 128-iteration scan, fixed accumulation order.
__global__ void gather_kernel(float* __restrict__ out)
{
    __shared__ int ps[N_EVENTS];
    const int tid = threadIdx.x;                 // 256 threads
    const int t0  = blockIdx.x * 256;
    const int t   = t0 + tid;

    if (tid < N_EVENTS) ps[tid] = g_pos[tid];
    __syncthreads();

    float acc = 0.0f;
    // fixed event order -> bit-deterministic float accumulation (no atomics)
    #pragma unroll 4
    for (int e = 0; e < N_EVENTS; e++) {
        const int p = ps[e];
        if (p < t0 + 256 && p + ATOM_SIZE > t0) {
            const unsigned off = (unsigned)(t - p);
            if (off < (unsigned)ATOM_SIZE) acc += g_wave[e * ATOM_SIZE + off];
        }
    }
    out[t] = acc;
}

// ---------------- launch -------------------------------------------------------
extern "C" void kernel_launch(void* const* d_in, const int* in_sizes, int n_in,
                              void* d_out, int out_size)
{
    // Robust input mapping by element count (all sizes unique except the two 16s,
    // where dict order gives base_latent before to_amp_W).
    const float *base_latent = nullptr, *Wt = nullptr, *Ws = nullptr, *bs = nullptr;
    const float *atoms = nullptr, *Wa = nullptr, *ba = nullptr, *Wamp = nullptr, *bamp = nullptr;
    for (int i = 0; i < n_in; i++) {
        const int s = in_sizes[i];
        const float* p = (const float*)d_in[i];
        switch (s) {
            case WT_ELEMS:              Wt = p;    break;   // 7616
            case WS_ELEMS:              Ws = p;    break;   // 3584
            case BS_ELEMS:              bs = p;    break;   // 224
            case N_ATOMS * ATOM_SIZE:   atoms = p; break;   // 16384
            case N_ATOMS * LATENT:      Wa = p;    break;   // 512
            case N_ATOMS:               ba = p;    break;   // 32
            case 1:                     bamp = p;  break;   // 1
            case LATENT:                                    // 16, twice
                if (!base_latent) base_latent = p; else Wamp = p;
                break;
            default: break;
        }
    }

    float* out = (float*)d_out;

    const int tree_smem = TREE_SMEM_FLOATS * (int)sizeof(float);   // ~94.6 KB
    cudaFuncSetAttribute(tree_kernel, cudaFuncAttributeMaxDynamicSharedMemorySize, tree_smem);

    tree_kernel<<<1, 1024, tree_smem>>>(base_latent, Wt, Ws, bs);
    wave_kernel<<<N_EVENTS, 128>>>(atoms, Wa, ba, Wamp, bamp);
    gather_kernel<<<N_SAMPLES / 256, 256>>>(out);
    (void)out_size;
}

// round 10
// speedup vs baseline: 4.7538x; 1.1846x over previous
#include <cuda_runtime.h>
#include <math.h>

#define N_SAMPLES 131072
#define N_EVENTS  128
#define N_ATOMS   32
#define ATOM_SIZE 512
#define LATENT    16
#define TIME_DIM  17
#define LAYERS    7

// ---------------- device-global scratch (no allocation allowed) ----------------
__device__ float g_xf[N_EVENTS * LATENT];            // final latent per event
__device__ int   g_pos[N_EVENTS];                    // dirac shift per event
__device__ float g_wave[N_EVENTS * ATOM_SIZE];       // pre-scaled waveforms

// 16-term dot product, serial FMA chain in ascending index order.
// EXACTLY the same association order as all prior passing kernels so the
// argmax bit decisions are bit-identical.
__device__ __forceinline__ float dot16(float4 w0, float4 w1, float4 w2, float4 w3,
                                       float4 x0, float4 x1, float4 x2, float4 x3,
                                       float init)
{
    float v = init;
    v = fmaf(x0.x, w0.x, v); v = fmaf(x0.y, w0.y, v);
    v = fmaf(x0.z, w0.z, v); v = fmaf(x0.w, w0.w, v);
    v = fmaf(x1.x, w1.x, v); v = fmaf(x1.y, w1.y, v);
    v = fmaf(x1.z, w1.z, v); v = fmaf(x1.w, w1.w, v);
    v = fmaf(x2.x, w2.x, v); v = fmaf(x2.y, w2.y, v);
    v = fmaf(x2.z, w2.z, v); v = fmaf(x2.w, w2.w, v);
    v = fmaf(x3.x, w3.x, v); v = fmaf(x3.y, w3.y, v);
    v = fmaf(x3.z, w3.z, v); v = fmaf(x3.w, w3.w, v);
    return v;
}

// sizes
#define WT_ELEMS (LAYERS * 68 * LATENT)   // 7616
#define WS_ELEMS (LAYERS * 32 * LATENT)   // 3584
#define BS_ELEMS (LAYERS * 32)            // 224
#define X_ELEMS  (N_EVENTS * LATENT)      // 2048
#define T_ELEMS  (N_EVENTS * 34)          // 4352
#define TREE_SMEM_FLOATS (2 * X_ELEMS + 2 * T_ELEMS)   // 12800 floats = 51.2 KB

// ---------------- K1: binary tree — register-stationary weights ---------------
// 1024 threads = 8 event-groups x 128 row-lanes.
//   r = tid & 127 : output row (r<68 time row; 68<=r<100 latent row; else idle)
//   g = tid >> 7  : event group; thread sweeps events e = g, g+8, g+16, ...
// Weight row loaded into registers ONCE per layer (coalesced LDG); x[e] reads
// are warp-uniform broadcast LDS.128 (all lanes in a warp share g -> same e).
__global__ __launch_bounds__(1024, 1)
void tree_kernel(const float* __restrict__ base_latent,
                 const float* __restrict__ Wt,   // (7, 68, 16)
                 const float* __restrict__ Ws,   // (7, 32, 16)
                 const float* __restrict__ bs)   // (7, 32)
{
    extern __shared__ float sm[];
    float* sx = sm;                        // 2 * 2048  ping-pong latent
    float* st = sm + 2 * X_ELEMS;          // 2 * 4352  ping-pong times

    const int tid = threadIdx.x;           // 1024 threads
    const int r   = tid & 127;             // row lane
    const int g   = tid >> 7;              // event group (0..7)

    if (tid < LATENT)       sx[tid] = base_latent[tid];
    if (tid < TIME_DIM * 2) st[tid] = 0.0f;
    __syncthreads();

    const bool is_time = (r < 68);
    const bool is_lat  = (r >= 68) && (r < 100);
    const int  c  = r / 34;                // time: child index
    const int  rr = r - c * 34;            // time: (t*2 + s)
    const int  jl = r - 68;                // latent row
    const int  ch = jl >> 4;               // latent: child index
    const int  sl = jl & 15;               // latent: slot

    for (int i = 0; i < LAYERS; i++) {
        // ---- weight row for this layer -> registers (coalesced, L1/L2-hot) ----
        float4 w0 = {0,0,0,0}, w1 = {0,0,0,0}, w2 = {0,0,0,0}, w3 = {0,0,0,0};
        float  bias = 0.0f;
        if (is_time) {
            const float4* wp = (const float4*)(Wt + (size_t)(i * 68 + r) * LATENT);
            w0 = wp[0]; w1 = wp[1]; w2 = wp[2]; w3 = wp[3];
        } else if (is_lat) {
            const float4* wp = (const float4*)(Ws + (size_t)(i * 32 + jl) * LATENT);
            w0 = wp[0]; w1 = wp[1]; w2 = wp[2]; w3 = wp[3];
            bias = bs[i * 32 + jl];
        }

        const int n = 1 << i;
        const float* xA = sx + (i & 1) * X_ELEMS;
        float*       xB = sx + ((i & 1) ^ 1) * X_ELEMS;
        const float* tA = st + (i & 1) * T_ELEMS;
        float*       tB = st + ((i & 1) ^ 1) * T_ELEMS;

        if (is_time) {
            for (int e = g; e < n; e += 8) {
                const float4* xp = (const float4*)(xA + e * LATENT);  // broadcast
                const float4 x0 = xp[0], x1 = xp[1], x2 = xp[2], x3 = xp[3];
                const float v = dot16(w0, w1, w2, w3, x0, x1, x2, x3, 0.0f);
                tB[(2 * e + c) * 34 + rr] = tA[e * 34 + rr] + v;
            }
        } else if (is_lat) {
            for (int e = g; e < n; e += 8) {
                const float4* xp = (const float4*)(xA + e * LATENT);  // broadcast
                const float4 x0 = xp[0], x1 = xp[1], x2 = xp[2], x3 = xp[3];
                const float v = dot16(w0, w1, w2, w3, x0, x1, x2, x3, bias);
                xB[(2 * e + ch) * LATENT + sl] = v;
            }
        }
        __syncthreads();
    }

    // LAYERS = 7 (odd) -> final buffers in parity 1
    const float* xF = sx + X_ELEMS;
    const float* tF = st + T_ELEMS;

    // export final latents
    for (int k = tid; k < X_ELEMS; k += 1024) g_xf[k] = xF[k];

    // argmax per event: strict >, MSB first (bit-identical to prior kernels)
    if (tid < N_EVENTS) {
        const int e = tid;
        int p = 0;
        #pragma unroll
        for (int t = 0; t < TIME_DIM; t++) {
            const int bit = tF[e * 34 + t * 2 + 1] > tF[e * 34 + t * 2 + 0];
            p |= bit << (TIME_DIM - 1 - t);
        }
        g_pos[e] = p;
    }
}

// ---------------- K2: per-event waveform (coeffs, window, norm, amp) -----------
// One block per event — parallel across events, immune to position clustering.
__global__ void wave_kernel(const float* __restrict__ atoms,   // (32, 512)
                            const float* __restrict__ Wa,      // (32, 16)
                            const float* __restrict__ ba,      // (32,)
                            const float* __restrict__ Wamp,    // (1, 16)
                            const float* __restrict__ bamp)    // (1,)
{
    __shared__ float cs[N_ATOMS];
    __shared__ float s_amp;
    __shared__ float s_red[4];

    const int e   = blockIdx.x;
    const int tid = threadIdx.x;          // 128 threads
    const float* xe = g_xf + e * LATENT;

    if (tid < N_ATOMS) {
        float v = ba[tid];
        #pragma unroll
        for (int d = 0; d < LATENT; d++) v += xe[d] * Wa[tid * LATENT + d];
        cs[tid] = v;
    }
    if (tid == N_ATOMS) {
        float v = bamp[0];
        #pragma unroll
        for (int d = 0; d < LATENT; d++) v += xe[d] * Wamp[d];
        s_amp = v;
    }
    __syncthreads();

    float w[4];
    float sq = 0.0f;
    #pragma unroll
    for (int q = 0; q < 4; q++) {
        const int j = tid + q * 128;
        float v = 0.0f;
        #pragma unroll
        for (int k = 0; k < N_ATOMS; k++) v += cs[k] * atoms[k * ATOM_SIZE + j];
        // Hamming window: 0.54 - 0.46*cos(2*pi*j/512)
        const float win = 0.54f - 0.46f * cospif((float)j * (1.0f / 256.0f));
        v *= win;
        w[q] = v;
        sq += v * v;
    }

    // block reduce sum of squares (4 warps)
    #pragma unroll
    for (int o = 16; o > 0; o >>= 1) sq += __shfl_xor_sync(0xffffffffu, sq, o);
    if ((tid & 31) == 0) s_red[tid >> 5] = sq;
    __syncthreads();
    const float tot   = s_red[0] + s_red[1] + s_red[2] + s_red[3];
    const float scale = s_amp / (sqrtf(tot) + 1e-8f);

    #pragma unroll
    for (int q = 0; q < 4; q++)
        g_wave[e * ATOM_SIZE + tid + q * 128] = w[q] * scale;
}

// ---------------- K3: deterministic gather of shifted waveforms ---------------
// Bounded cost per tile: fixed 128-iteration scan, fixed accumulation order.
__global__ void gather_kernel(float* __restrict__ out)
{
    __shared__ int ps[N_EVENTS];
    const int tid = threadIdx.x;                 // 256 threads
    const int t0  = blockIdx.x * 256;
    const int t   = t0 + tid;

    if (tid < N_EVENTS) ps[tid] = g_pos[tid];
    __syncthreads();

    float acc = 0.0f;
    // fixed event order -> bit-deterministic float accumulation (no atomics)
    #pragma unroll 4
    for (int e = 0; e < N_EVENTS; e++) {
        const int p = ps[e];
        if (p < t0 + 256 && p + ATOM_SIZE > t0) {
            const unsigned off = (unsigned)(t - p);
            if (off < (unsigned)ATOM_SIZE) acc += g_wave[e * ATOM_SIZE + off];
        }
    }
    out[t] = acc;
}

// ---------------- launch -------------------------------------------------------
extern "C" void kernel_launch(void* const* d_in, const int* in_sizes, int n_in,
                              void* d_out, int out_size)
{
    // Robust input mapping by element count (all sizes unique except the two 16s,
    // where dict order gives base_latent before to_amp_W).
    const float *base_latent = nullptr, *Wt = nullptr, *Ws = nullptr, *bs = nullptr;
    const float *atoms = nullptr, *Wa = nullptr, *ba = nullptr, *Wamp = nullptr, *bamp = nullptr;
    for (int i = 0; i < n_in; i++) {
        const int s = in_sizes[i];
        const float* p = (const float*)d_in[i];
        switch (s) {
            case WT_ELEMS:              Wt = p;    break;   // 7616
            case WS_ELEMS:              Ws = p;    break;   // 3584
            case BS_ELEMS:              bs = p;    break;   // 224
            case N_ATOMS * ATOM_SIZE:   atoms = p; break;   // 16384
            case N_ATOMS * LATENT:      Wa = p;    break;   // 512
            case N_ATOMS:               ba = p;    break;   // 32
            case 1:                     bamp = p;  break;   // 1
            case LATENT:                                    // 16, twice
                if (!base_latent) base_latent = p; else Wamp = p;
                break;
            default: break;
        }
    }

    float* out = (float*)d_out;

    const int tree_smem = TREE_SMEM_FLOATS * (int)sizeof(float);   // 51.2 KB
    cudaFuncSetAttribute(tree_kernel, cudaFuncAttributeMaxDynamicSharedMemorySize, tree_smem);

    tree_kernel<<<1, 1024, tree_smem>>>(base_latent, Wt, Ws, bs);
    wave_kernel<<<N_EVENTS, 128>>>(atoms, Wa, ba, Wamp, bamp);
    gather_kernel<<<N_SAMPLES / 256, 256>>>(out);
    (void)out_size;
}